// round 1
// baseline (speedup 1.0000x reference)
#include <cuda_runtime.h>
#include <math.h>

// Problem constants
#define BATCH 4
#define SEQ   2048
#define DEMB  512
#define NHEAD 8
#define DHEAD 64
#define DMODL 512              // NHEAD*DHEAD
#define MROWS (BATCH*SEQ)      // 8192

// ---------------- scratch (device globals; no allocation) ----------------
__device__ float g_z [MROWS * DEMB];   // x + pe
__device__ float g_q [MROWS * DMODL];  // [B,H,S,Dh]
__device__ float g_k [MROWS * DMODL];
__device__ float g_v [MROWS * DMODL];
__device__ float g_h [MROWS * DMODL];  // attention out, [B,S,H*Dh]
__device__ float g_z2[MROWS * DEMB];   // z + h@Wo + bo
__device__ float g_f [MROWS * DEMB];   // leaky(z2@W1+b1)

// ---------------- 1) positional encoding add ----------------
__global__ void pe_add_kernel(const float* __restrict__ x, float* __restrict__ z) {
    int idx = blockIdx.x * blockDim.x + threadIdx.x;   // over MROWS*DEMB
    if (idx >= MROWS * DEMB) return;
    int d = idx & (DEMB - 1);
    int s = (idx >> 9) & (SEQ - 1);
    int i2 = (d >> 1) * 2;
    // div = exp(-(2i) * ln(10000)/512)
    float divv = expf(-(float)i2 * (9.210340371976184f / 512.0f));
    float ang = (float)s * divv;
    float pe = (d & 1) ? cosf(ang) : sinf(ang);
    z[idx] = x[idx] + pe;
}

// ---------------- 2) tiled SGEMM, M=8192, K=512, N=512 ----------------
// C = A[M,K] @ W[K,N] + bias, with epilogue MODE:
//   0: QKV head scatter into [B,H,S,Dh]
//   1: residual add (C = resid + ...)
//   2: leaky relu
#define BM 64
#define BN 64
#define BKK 16

template<int MODE>
__global__ __launch_bounds__(256)
void gemm_kernel(const float* __restrict__ A, const float* __restrict__ W,
                 const float* __restrict__ bias, const float* __restrict__ resid,
                 float* __restrict__ C) {
    const int K = 512, N = 512;
    __shared__ float As[BKK][BM];
    __shared__ float Bs[BKK][BN];

    int bm = blockIdx.y * BM;
    int bn = blockIdx.x * BN;
    int tid = threadIdx.x;
    int tx = tid & 15;
    int ty = tid >> 4;

    // A-tile load: 64 rows x 16 k ; each thread one float4 along K
    int arow = tid >> 2;           // 0..63
    int akv  = (tid & 3) * 4;      // 0,4,8,12
    // B-tile load: 16 rows x 64 n ; each thread one float4 along N
    int brow = tid >> 4;           // 0..15
    int bcol = (tid & 15) * 4;

    float acc[4][4];
#pragma unroll
    for (int i = 0; i < 4; i++)
#pragma unroll
        for (int j = 0; j < 4; j++) acc[i][j] = 0.0f;

    for (int k0 = 0; k0 < K; k0 += BKK) {
        float4 a4 = *(const float4*)&A[(size_t)(bm + arow) * K + k0 + akv];
        As[akv + 0][arow] = a4.x;
        As[akv + 1][arow] = a4.y;
        As[akv + 2][arow] = a4.z;
        As[akv + 3][arow] = a4.w;
        *(float4*)&Bs[brow][bcol] = *(const float4*)&W[(size_t)(k0 + brow) * N + bn + bcol];
        __syncthreads();

#pragma unroll
        for (int kk = 0; kk < BKK; kk++) {
            float4 a = *(const float4*)&As[kk][ty * 4];
            float4 b = *(const float4*)&Bs[kk][tx * 4];
            acc[0][0] += a.x * b.x; acc[0][1] += a.x * b.y; acc[0][2] += a.x * b.z; acc[0][3] += a.x * b.w;
            acc[1][0] += a.y * b.x; acc[1][1] += a.y * b.y; acc[1][2] += a.y * b.z; acc[1][3] += a.y * b.w;
            acc[2][0] += a.z * b.x; acc[2][1] += a.z * b.y; acc[2][2] += a.z * b.z; acc[2][3] += a.z * b.w;
            acc[3][0] += a.w * b.x; acc[3][1] += a.w * b.y; acc[3][2] += a.w * b.z; acc[3][3] += a.w * b.w;
        }
        __syncthreads();
    }

    int m0 = bm + ty * 4;
    int n0 = bn + tx * 4;
#pragma unroll
    for (int i = 0; i < 4; i++) {
        int m = m0 + i;
#pragma unroll
        for (int j = 0; j < 4; j++) {
            int n = n0 + j;
            float val = acc[i][j] + bias[n];
            if (MODE == 0) {
                // scatter to q/k/v layout [B,H,S,Dh]
                int b = m >> 11;            // /2048
                int s = m & (SEQ - 1);
                int h = n >> 6;
                int dh = n & 63;
                C[((((size_t)b * NHEAD + h) * SEQ + s) << 6) + dh] = val;
            } else if (MODE == 1) {
                val += resid[(size_t)m * N + n];
                C[(size_t)m * N + n] = val;
            } else {
                C[(size_t)m * N + n] = (val > 0.0f) ? val : 0.01f * val;
            }
        }
    }
}

// ---------------- 3) fused flash-style attention ----------------
// grid: (B*H, SEQ/128), 128 threads; each thread owns one query row.
__global__ __launch_bounds__(128)
void attn_kernel(const float* __restrict__ q, const float* __restrict__ k,
                 const float* __restrict__ v, float* __restrict__ hout) {
    __shared__ float Ksh[64 * 64];
    __shared__ float Vsh[64 * 64];

    int bh = blockIdx.x;                   // 0..31
    int qt = blockIdx.y;                   // 0..15
    int tid = threadIdx.x;                 // 0..127
    int qrow = qt * 128 + tid;

    const float* qp = q + ((size_t)bh * SEQ + qrow) * DHEAD;
    float qr[64];
#pragma unroll
    for (int d4 = 0; d4 < 16; d4++) {
        float4 t = *(const float4*)&qp[d4 * 4];
        qr[4 * d4 + 0] = t.x; qr[4 * d4 + 1] = t.y;
        qr[4 * d4 + 2] = t.z; qr[4 * d4 + 3] = t.w;
    }

    float o[64];
#pragma unroll
    for (int d = 0; d < 64; d++) o[d] = 0.0f;
    float mrun = -1e30f, lrun = 0.0f;
    const float scale = 0.125f;            // 1/sqrt(64)

    for (int kt = 0; kt < SEQ / 64; kt++) {
        const float4* kp = (const float4*)(k + ((size_t)bh * SEQ + kt * 64) * DHEAD);
        const float4* vp = (const float4*)(v + ((size_t)bh * SEQ + kt * 64) * DHEAD);
#pragma unroll
        for (int i = 0; i < 8; i++) {
            ((float4*)Ksh)[i * 128 + tid] = kp[i * 128 + tid];
            ((float4*)Vsh)[i * 128 + tid] = vp[i * 128 + tid];
        }
        __syncthreads();

        float sc[64];
        float tmax = mrun;
#pragma unroll
        for (int j = 0; j < 64; j++) {
            const float4* kr = (const float4*)&Ksh[j * 64];
            float s = 0.0f;
#pragma unroll
            for (int d4 = 0; d4 < 16; d4++) {
                float4 kk = kr[d4];
                s += qr[4 * d4 + 0] * kk.x + qr[4 * d4 + 1] * kk.y
                   + qr[4 * d4 + 2] * kk.z + qr[4 * d4 + 3] * kk.w;
            }
            s *= scale;
            sc[j] = s;
            tmax = fmaxf(tmax, s);
        }

        float corr = __expf(mrun - tmax);
        mrun = tmax;
        lrun *= corr;
#pragma unroll
        for (int d = 0; d < 64; d++) o[d] *= corr;

#pragma unroll
        for (int j = 0; j < 64; j++) {
            float p = __expf(sc[j] - mrun);
            lrun += p;
            const float4* vr = (const float4*)&Vsh[j * 64];
#pragma unroll
            for (int d4 = 0; d4 < 16; d4++) {
                float4 vv = vr[d4];
                o[4 * d4 + 0] += p * vv.x; o[4 * d4 + 1] += p * vv.y;
                o[4 * d4 + 2] += p * vv.z; o[4 * d4 + 3] += p * vv.w;
            }
        }
        __syncthreads();
    }

    float inv = 1.0f / lrun;
    int b = bh >> 3, h = bh & 7;
    float* op = hout + ((((size_t)b * SEQ + qrow) * NHEAD + h) << 6);
#pragma unroll
    for (int d4 = 0; d4 < 16; d4++) {
        float4 t;
        t.x = o[4 * d4 + 0] * inv; t.y = o[4 * d4 + 1] * inv;
        t.z = o[4 * d4 + 2] * inv; t.w = o[4 * d4 + 3] * inv;
        *(float4*)&op[d4 * 4] = t;
    }
}

// ---------------- launcher ----------------
extern "C" void kernel_launch(void* const* d_in, const int* in_sizes, int n_in,
                              void* d_out, int out_size) {
    const float* x  = (const float*)d_in[0];
    const float* Wq = (const float*)d_in[1];
    const float* bq = (const float*)d_in[2];
    const float* Wk = (const float*)d_in[3];
    const float* bk = (const float*)d_in[4];
    const float* Wv = (const float*)d_in[5];
    const float* bv = (const float*)d_in[6];
    const float* Wo = (const float*)d_in[7];
    const float* bo = (const float*)d_in[8];
    const float* W1 = (const float*)d_in[9];
    const float* b1 = (const float*)d_in[10];
    const float* W2 = (const float*)d_in[11];
    const float* b2 = (const float*)d_in[12];
    float* out = (float*)d_out;

    float *z, *q, *k, *v, *h, *z2, *f;
    cudaGetSymbolAddress((void**)&z,  g_z);
    cudaGetSymbolAddress((void**)&q,  g_q);
    cudaGetSymbolAddress((void**)&k,  g_k);
    cudaGetSymbolAddress((void**)&v,  g_v);
    cudaGetSymbolAddress((void**)&h,  g_h);
    cudaGetSymbolAddress((void**)&z2, g_z2);
    cudaGetSymbolAddress((void**)&f,  g_f);

    // 1) z = x + pe
    pe_add_kernel<<<(MROWS * DEMB) / 256, 256>>>(x, z);

    // 2) Q, K, V projections with head scatter
    dim3 gg(DMODL / BN, MROWS / BM);   // (8, 128)
    gemm_kernel<0><<<gg, 256>>>(z, Wq, bq, nullptr, q);
    gemm_kernel<0><<<gg, 256>>>(z, Wk, bk, nullptr, k);
    gemm_kernel<0><<<gg, 256>>>(z, Wv, bv, nullptr, v);

    // 3) attention
    attn_kernel<<<dim3(BATCH * NHEAD, SEQ / 128), 128>>>(q, k, v, h);

    // 4) out projection + residual
    gemm_kernel<1><<<gg, 256>>>(h, Wo, bo, z, z2);

    // 5) FFN
    gemm_kernel<2><<<gg, 256>>>(z2, W1, b1, nullptr, f);
    gemm_kernel<2><<<gg, 256>>>(f,  W2, b2, nullptr, out);
}